// round 16
// baseline (speedup 1.0000x reference)
#include <cuda_runtime.h>
#include <cuda_bf16.h>
#include <math.h>
#include <stdint.h>

#define NTOK 4096
#define DIM  1024
#define D3   3072
#define NH   16
#define HDIM 64
#define SEQ  1024
#define FF   4096
#define NEXP 8
#define CAPN 2048
#define NEGV -1e30f

// ---------------- device scratch ----------------
__device__ float g_qkv[12582912];
__device__ float g_qh [4194304];
__device__ float g_kh [4194304];
__device__ float g_vh [4194304];
__device__ float g_sc [67108864];          // scores; later reused as MoE h [8,2048,4096]
__device__ float g_ao [4194304];
__device__ float g_tmp[4194304];
__device__ float g_x1 [4194304];
__device__ float g_logits[NTOK * NEXP];
__device__ float g_tv[NTOK * 2];
__device__ int   g_ti[NTOK * 2];
__device__ int   g_tok[NEXP * CAPN];
__device__ float g_w  [NEXP * CAPN];
__device__ int   g_cnt[NEXP];
__device__ float g_moe[4194304];
__device__ float g_cos[SEQ * 32];
__device__ float g_sin[SEQ * 32];
// 3-term split buffers (attention projection GEMMs)
__device__ __nv_bfloat16 g_xc  [12582912];
__device__ __nv_bfloat16 g_wipc[ 9437184];
__device__ __nv_bfloat16 g_qc  [12582912];
__device__ __nv_bfloat16 g_kc  [12582912];
__device__ __nv_bfloat16 g_vc  [12582912];
__device__ __nv_bfloat16 g_aoc [12582912];
__device__ __nv_bfloat16 g_wopc[ 3145728];
// 3-term split buffers (MoE path)
__device__ __nv_bfloat16 g_x1c [12582912];
__device__ __nv_bfloat16 g_gwc [100663296];
__device__ __nv_bfloat16 g_vwc [100663296];
__device__ __nv_bfloat16 g_woc [100663296];
__device__ __nv_bfloat16 g_hc  [201326592];

// ---------------- helpers ----------------
__device__ __forceinline__ uint32_t smem_u32(const void* p) {
    uint32_t a;
    asm("{ .reg .u64 t; cvta.to.shared.u64 t, %1; cvt.u32.u64 %0, t; }" : "=r"(a) : "l"(p));
    return a;
}
#define SWZ128(o) ((o) ^ (((o) >> 3) & 0x70))
#define LDSM4(r0, r1, r2, r3, addr) \
    asm volatile("ldmatrix.sync.aligned.m8n8.x4.shared.b16 {%0,%1,%2,%3}, [%4];" \
        : "=r"(r0), "=r"(r1), "=r"(r2), "=r"(r3) : "r"(addr))
#define MMA16816(d, a, b) \
    asm volatile("mma.sync.aligned.m16n8k16.row.col.f32.bf16.bf16.f32 " \
        "{%0,%1,%2,%3}, {%4,%5,%6,%7}, {%8,%9}, {%0,%1,%2,%3};" \
        : "+f"((d)[0]), "+f"((d)[1]), "+f"((d)[2]), "+f"((d)[3]) \
        : "r"((a)[0]), "r"((a)[1]), "r"((a)[2]), "r"((a)[3]), "r"((b)[0]), "r"((b)[1]))
#define CP_ASYNC16(dst, src) \
    asm volatile("cp.async.cg.shared.global [%0], [%1], 16;" :: "r"(dst), "l"(src))
#define CP_COMMIT() asm volatile("cp.async.commit_group;")
#define CP_WAIT0()  asm volatile("cp.async.wait_group 0;")

__device__ __forceinline__ void split_bf16(float v, __nv_bfloat16& h, __nv_bfloat16& l) {
    h = __float2bfloat16(v);
    l = __float2bfloat16(v - __bfloat162float(h));
}

// FMA-only exp: range-reduce base-2, degree-6 Taylor of 2^f on [0,1).
// Max relative error ~2e-6. No MUFU.
__device__ __forceinline__ float fexp(float x) {
    x = fminf(fmaxf(x, -87.0f), 87.0f);
    float t = x * 1.4426950408889634f;
    float n = floorf(t);
    float f = t - n;
    float p = 1.3333558146428443e-3f;
    p = fmaf(p, f, 9.6181291076284772e-3f);
    p = fmaf(p, f, 5.5504108664821580e-2f);
    p = fmaf(p, f, 2.4022650695910072e-1f);
    p = fmaf(p, f, 6.9314718055994531e-1f);
    p = fmaf(p, f, 1.0f);
    float s = __int_as_float(((int)n + 127) << 23);
    return p * s;
}

__device__ __forceinline__ float blocksum256(float v, float* sh) {
    int t = threadIdx.x;
#pragma unroll
    for (int o = 16; o; o >>= 1) v += __shfl_xor_sync(0xFFFFFFFFu, v, o);
    __syncthreads();
    if ((t & 31) == 0) sh[t >> 5] = v;
    __syncthreads();
    float tot = 0.f;
#pragma unroll
    for (int i = 0; i < 8; i++) tot += sh[i];
    return tot;
}

// ============ warp-MMA GEMM: 128x128 block, 4 warps (64x64 warp tile) ============
__global__ void __launch_bounds__(128, 2) gemm_mma(
    const __nv_bfloat16* __restrict__ A, long lda, long szA,
    const __nv_bfloat16* __restrict__ B, long ldb, long szB,
    const float* __restrict__ bias, float scale,
    float* __restrict__ C, long ldc, int zdiv, long szC1, long szC2, int K3)
{
    extern __shared__ char sm[];
    char* sA = sm;
    char* sB = sm + 32768;
    const int tid = threadIdx.x, w = tid >> 5, lane = tid & 31;
    const int wm = (w & 1) * 64, wn = (w >> 1) * 64;

    const long z = blockIdx.z;
    const __nv_bfloat16* Az = A + z * szA + (long)(blockIdx.x * 128) * lda;
    const __nv_bfloat16* Bz = B + z * szB + (long)(blockIdx.y * 128) * ldb;
    const int nchunk = K3 >> 6;
    uint32_t sAu = smem_u32(sA), sBu = smem_u32(sB);

#define CPA(s, c) { _Pragma("unroll") for (int i = 0; i < 8; i++) { \
        int idx = tid + i * 128, r = idx >> 3, cc = idx & 7; \
        CP_ASYNC16(sAu + (s) * 16384 + SWZ128(r * 128 + cc * 16), \
                   Az + (long)r * lda + (c) * 64 + cc * 8); } \
    _Pragma("unroll") for (int i = 0; i < 8; i++) { \
        int idx = tid + i * 128, r = idx >> 3, cc = idx & 7; \
        CP_ASYNC16(sBu + (s) * 16384 + SWZ128(r * 128 + cc * 16), \
                   Bz + (long)r * ldb + (c) * 64 + cc * 8); } }

    float acc[4][8][4] = {};
    CPA(0, 0); CP_COMMIT();
    CP_WAIT0(); __syncthreads();

    for (int c = 0; c < nchunk; c++) {
        if (c + 1 < nchunk) { CPA((c + 1) & 1, c + 1); CP_COMMIT(); }
        char* a0 = sA + (c & 1) * 16384;
        char* b0 = sB + (c & 1) * 16384;
#pragma unroll
        for (int ks = 0; ks < 4; ks++) {
            uint32_t af[4][4];
#pragma unroll
            for (int mi = 0; mi < 4; mi++) {
                uint32_t ad = smem_u32(a0 + SWZ128((wm + mi * 16 + (lane & 15)) * 128 +
                                                   ks * 32 + (lane >> 4) * 16));
                LDSM4(af[mi][0], af[mi][1], af[mi][2], af[mi][3], ad);
            }
            uint32_t bf[8][2];
#pragma unroll
            for (int j = 0; j < 4; j++) {
                uint32_t r0, r1, r2, r3;
                uint32_t bd = smem_u32(b0 + SWZ128((wn + j * 16 + (lane & 15)) * 128 +
                                                   ks * 32 + (lane >> 4) * 16));
                LDSM4(r0, r1, r2, r3, bd);
                bf[2 * j][0] = r0; bf[2 * j][1] = r2;
                bf[2 * j + 1][0] = r1; bf[2 * j + 1][1] = r3;
            }
#pragma unroll
            for (int mi = 0; mi < 4; mi++)
#pragma unroll
                for (int nj = 0; nj < 8; nj++)
                    MMA16816(acc[mi][nj], af[mi], bf[nj]);
        }
        if (c + 1 < nchunk) CP_WAIT0();
        __syncthreads();
    }
#undef CPA

    long coff = (long)(z / zdiv) * szC1 + (long)(z % zdiv) * szC2;
    int m0 = blockIdx.x * 128 + wm + (lane >> 2);
    int nb = blockIdx.y * 128 + wn + (lane & 3) * 2;
#pragma unroll
    for (int mi = 0; mi < 4; mi++) {
        float* rp0 = C + coff + (long)(m0 + mi * 16) * ldc;
        float* rp1 = rp0 + 8 * ldc;
#pragma unroll
        for (int nj = 0; nj < 8; nj++) {
            int n = nb + nj * 8;
            float b0v = 0.f, b1v = 0.f;
            if (bias) { b0v = bias[n]; b1v = bias[n + 1]; }
            float2 o0 = make_float2(acc[mi][nj][0] * scale + b0v, acc[mi][nj][1] * scale + b1v);
            float2 o1 = make_float2(acc[mi][nj][2] * scale + b0v, acc[mi][nj][3] * scale + b1v);
            *(float2*)(rp0 + n) = o0;
            *(float2*)(rp1 + n) = o1;
        }
    }
}

// ============ fused MoE gate+val GEMMs + silu (poly-exp), fp32 h out ============
__global__ void __launch_bounds__(128, 2) moe_gatval_mma(
    const float* __restrict__ gb, const float* __restrict__ vb, float* __restrict__ Hout)
{
    extern __shared__ char sm[];
    char* sA = sm;
    char* sG = sm + 32768;
    char* sV = sm + 49152;
    int* s_tok = (int*)(sm + 65536);
    const int e = blockIdx.z, bm = blockIdx.x * 128;
    if (bm >= g_cnt[e]) return;
    const int tid = threadIdx.x, w = tid >> 5, lane = tid & 31;
    const int wm = (w & 1) * 64, wn = (w >> 1) * 32;

    s_tok[tid] = g_tok[e * CAPN + bm + tid];
    __syncthreads();

    const __nv_bfloat16* Bg = g_gwc + (long)e * FF * 3072 + (long)(blockIdx.y * 64) * 3072;
    const __nv_bfloat16* Bv = g_vwc + (long)e * FF * 3072 + (long)(blockIdx.y * 64) * 3072;
    uint32_t sAu = smem_u32(sA), sGu = smem_u32(sG), sVu = smem_u32(sV);

#define CPA(s, c) { _Pragma("unroll") for (int i = 0; i < 8; i++) { \
        int idx = tid + i * 128, r = idx >> 3, cc = idx & 7; \
        CP_ASYNC16(sAu + (s) * 16384 + SWZ128(r * 128 + cc * 16), \
                   g_x1c + (long)s_tok[r] * 3072 + (c) * 64 + cc * 8); } \
    _Pragma("unroll") for (int i = 0; i < 4; i++) { \
        int idx = tid + i * 128, r = idx >> 3, cc = idx & 7; \
        CP_ASYNC16(sGu + (s) * 8192 + SWZ128(r * 128 + cc * 16), \
                   Bg + (long)r * 3072 + (c) * 64 + cc * 8); \
        CP_ASYNC16(sVu + (s) * 8192 + SWZ128(r * 128 + cc * 16), \
                   Bv + (long)r * 3072 + (c) * 64 + cc * 8); } }

    float ag[4][4][4] = {}, av[4][4][4] = {};
    CPA(0, 0); CP_COMMIT();
    CP_WAIT0(); __syncthreads();

    for (int c = 0; c < 48; c++) {
        if (c + 1 < 48) { CPA((c + 1) & 1, c + 1); CP_COMMIT(); }
        char* a0 = sA + (c & 1) * 16384;
        char* gg0 = sG + (c & 1) * 8192;
        char* vv0 = sV + (c & 1) * 8192;
#pragma unroll
        for (int ks = 0; ks < 4; ks++) {
            uint32_t af[4][4];
#pragma unroll
            for (int mi = 0; mi < 4; mi++) {
                uint32_t ad = smem_u32(a0 + SWZ128((wm + mi * 16 + (lane & 15)) * 128 +
                                                   ks * 32 + (lane >> 4) * 16));
                LDSM4(af[mi][0], af[mi][1], af[mi][2], af[mi][3], ad);
            }
            uint32_t gf[4][2], vf[4][2];
#pragma unroll
            for (int j = 0; j < 2; j++) {
                uint32_t r0, r1, r2, r3;
                uint32_t gd = smem_u32(gg0 + SWZ128((wn + j * 16 + (lane & 15)) * 128 +
                                                    ks * 32 + (lane >> 4) * 16));
                LDSM4(r0, r1, r2, r3, gd);
                gf[2 * j][0] = r0; gf[2 * j][1] = r2;
                gf[2 * j + 1][0] = r1; gf[2 * j + 1][1] = r3;
                uint32_t vd = smem_u32(vv0 + SWZ128((wn + j * 16 + (lane & 15)) * 128 +
                                                    ks * 32 + (lane >> 4) * 16));
                LDSM4(r0, r1, r2, r3, vd);
                vf[2 * j][0] = r0; vf[2 * j][1] = r2;
                vf[2 * j + 1][0] = r1; vf[2 * j + 1][1] = r3;
            }
#pragma unroll
            for (int mi = 0; mi < 4; mi++)
#pragma unroll
                for (int nj = 0; nj < 4; nj++) {
                    MMA16816(ag[mi][nj], af[mi], gf[nj]);
                    MMA16816(av[mi][nj], af[mi], vf[nj]);
                }
        }
        if (c + 1 < 48) CP_WAIT0();
        __syncthreads();
    }
#undef CPA

    int m0 = bm + wm + (lane >> 2);
    int nb = blockIdx.y * 64 + wn + (lane & 3) * 2;
#pragma unroll
    for (int mi = 0; mi < 4; mi++) {
#pragma unroll
        for (int nj = 0; nj < 4; nj++) {
            int n = nb + nj * 8;
            float gb0 = gb[e * FF + n], gb1 = gb[e * FF + n + 1];
            float vb0 = vb[e * FF + n], vb1 = vb[e * FF + n + 1];
#pragma unroll
            for (int half = 0; half < 2; half++) {
                int m = m0 + mi * 16 + half * 8;
                float gt0 = ag[mi][nj][half * 2]     + gb0;
                float gt1 = ag[mi][nj][half * 2 + 1] + gb1;
                float vl0 = av[mi][nj][half * 2]     + vb0;
                float vl1 = av[mi][nj][half * 2 + 1] + vb1;
                float h0 = vl0 * (gt0 / (1.f + fexp(-gt0)));
                float h1 = vl1 * (gt1 / (1.f + fexp(-gt1)));
                float* dst = Hout + ((long)e * CAPN + m) * FF + n;
                dst[0] = h0; dst[1] = h1;
            }
        }
    }
}

// ============ MoE wo GEMM + weighted atomic scatter ============
__global__ void __launch_bounds__(128, 2) moe_wo_mma(const float* __restrict__ wob)
{
    extern __shared__ char sm[];
    char* sA = sm;
    char* sB = sm + 32768;
    const int e = blockIdx.z, bm = blockIdx.x * 128;
    const int cnt = g_cnt[e];
    if (bm >= cnt) return;
    const int tid = threadIdx.x, w = tid >> 5, lane = tid & 31;
    const int wm = (w & 1) * 64, wn = (w >> 1) * 64;

    const __nv_bfloat16* Az = g_hc + ((long)e * CAPN + bm) * 12288;
    const __nv_bfloat16* Bz = g_woc + (long)e * DIM * 12288 + (long)(blockIdx.y * 128) * 12288;
    uint32_t sAu = smem_u32(sA), sBu = smem_u32(sB);

#define CPA(s, c) { _Pragma("unroll") for (int i = 0; i < 8; i++) { \
        int idx = tid + i * 128, r = idx >> 3, cc = idx & 7; \
        CP_ASYNC16(sAu + (s) * 16384 + SWZ128(r * 128 + cc * 16), \
                   Az + (long)r * 12288 + (c) * 64 + cc * 8); \
        CP_ASYNC16(sBu + (s) * 16384 + SWZ128(r * 128 + cc * 16), \
                   Bz + (long)r * 12288 + (c) * 64 + cc * 8); } }

    float acc[4][8][4] = {};
    CPA(0, 0); CP_COMMIT();
    CP_WAIT0(); __syncthreads();

    for (int c = 0; c < 192; c++) {
        if (c + 1 < 192) { CPA((c + 1) & 1, c + 1); CP_COMMIT(); }
        char* a0 = sA + (c & 1) * 16384;
        char* b0 = sB + (c & 1) * 16384;
#pragma unroll
        for (int ks = 0; ks < 4; ks++) {
            uint32_t af[4][4];
#pragma unroll
            for (int mi = 0; mi < 4; mi++) {
                uint32_t ad = smem_u32(a0 + SWZ128((wm + mi * 16 + (lane & 15)) * 128 +
                                                   ks * 32 + (lane >> 4) * 16));
                LDSM4(af[mi][0], af[mi][1], af[mi][2], af[mi][3], ad);
            }
            uint32_t bfr[8][2];
#pragma unroll
            for (int j = 0; j < 4; j++) {
                uint32_t r0, r1, r2, r3;
                uint32_t bd = smem_u32(b0 + SWZ128((wn + j * 16 + (lane & 15)) * 128 +
                                                   ks * 32 + (lane >> 4) * 16));
                LDSM4(r0, r1, r2, r3, bd);
                bfr[2 * j][0] = r0; bfr[2 * j][1] = r2;
                bfr[2 * j + 1][0] = r1; bfr[2 * j + 1][1] = r3;
            }
#pragma unroll
            for (int mi = 0; mi < 4; mi++)
#pragma unroll
                for (int nj = 0; nj < 8; nj++)
                    MMA16816(acc[mi][nj], af[mi], bfr[nj]);
        }
        if (c + 1 < 192) CP_WAIT0();
        __syncthreads();
    }
#undef CPA

    int m0 = bm + wm + (lane >> 2);
    int nb = blockIdx.y * 128 + wn + (lane & 3) * 2;
#pragma unroll
    for (int mi = 0; mi < 4; mi++) {
#pragma unroll
        for (int half = 0; half < 2; half++) {
            int m = m0 + mi * 16 + half * 8;
            if (m < cnt) {
                int tok = g_tok[e * CAPN + m];
                float wt = g_w[e * CAPN + m];
                float* dst = g_moe + (long)tok * DIM;
#pragma unroll
                for (int nj = 0; nj < 8; nj++) {
                    int n = nb + nj * 8;
                    atomicAdd(dst + n,     (acc[mi][nj][half * 2]     + wob[e * DIM + n])     * wt);
                    atomicAdd(dst + n + 1, (acc[mi][nj][half * 2 + 1] + wob[e * DIM + n + 1]) * wt);
                }
            }
        }
    }
}

// ---------------- conversions ----------------
__global__ void conv3_k(const float* __restrict__ src, long ldsrc,
                        __nv_bfloat16* __restrict__ dst, int kshift, int patB, long total) {
    long idx = (long)blockIdx.x * 256 + threadIdx.x;
    if (idx >= total) return;
    long K = 1L << kshift;
    long r = idx >> kshift;
    int k = (int)(idx & (K - 1));
    float v = src[r * ldsrc + k];
    __nv_bfloat16 h, l; split_bf16(v, h, l);
    __nv_bfloat16* d = dst + r * (3L << kshift) + k;
    d[0] = h; d[K] = patB ? l : h; d[2 * K] = patB ? h : l;
}

// ---------------- RoPE ----------------
__global__ void rope_tables_k() {
    int idx = blockIdx.x * blockDim.x + threadIdx.x;
    if (idx >= SEQ * 32) return;
    int s = idx >> 5, i = idx & 31;
    float inv = powf(10000.f, -(float)i / 32.f);
    float ang = (float)s * inv;
    g_cos[idx] = (float)cos((double)ang);
    g_sin[idx] = (float)sin((double)ang);
}

__global__ void rope_apply_k() {
    int gid = blockIdx.x * blockDim.x + threadIdx.x;
    int i = gid & 31;
    int h = (gid >> 5) & 15;
    int n = (gid >> 9) & (NTOK - 1);
    int t = gid >> 21;
    int s = n & (SEQ - 1);
    float c = g_cos[s * 32 + i], sn = g_sin[s * 32 + i];
    float* base = g_qkv + (size_t)n * D3 + t * DIM + h * HDIM;
    float x1v = base[i], x2v = base[i + 32];
    base[i]      = x1v * c - x2v * sn;
    base[i + 32] = x2v * c + x1v * sn;
}

// ---------------- attention fp32 (R1 certified) ----------------
__device__ __forceinline__ void stage4(float S[16][64], int lc, int lr, float4 v) {
    S[lc + 0][lr] = v.x; S[lc + 1][lr] = v.y; S[lc + 2][lr] = v.z; S[lc + 3][lr] = v.w;
}
__device__ __forceinline__ void mma16f(float A[16][64], float B[16][64],
                                       float acc[4][4], int ty, int tx) {
#pragma unroll
    for (int kk = 0; kk < 16; kk++) {
        float4 a = *(const float4*)&A[kk][ty * 4];
        float4 b = *(const float4*)&B[kk][tx * 4];
        float av[4] = {a.x, a.y, a.z, a.w};
        float bv[4] = {b.x, b.y, b.z, b.w};
#pragma unroll
        for (int i = 0; i < 4; i++)
#pragma unroll
            for (int j = 0; j < 4; j++)
                acc[i][j] = fmaf(av[i], bv[j], acc[i][j]);
    }
}

__global__ void attn_scores_k() {
    __shared__ __align__(16) float As[16][64];
    __shared__ __align__(16) float Bs[16][64];
    int z = blockIdx.z, b = z >> 4, h = z & 15;
    const float* Abase = g_qh + (size_t)b * SEQ * DIM + h * HDIM;
    const float* Bbase = g_kh + (size_t)b * SEQ * DIM + h * HDIM;
    float* C = g_sc + (size_t)z * SEQ * SEQ;
    int tid = threadIdx.x, lr = tid >> 2, lc = (tid & 3) << 2, tx = tid & 15, ty = tid >> 4;
    const float* Ag = Abase + (size_t)(blockIdx.y * 64 + lr) * DIM + lc;
    const float* Bg = Bbase + (size_t)(blockIdx.x * 64 + lr) * DIM + lc;
    float acc[4][4] = {};
#pragma unroll
    for (int k0 = 0; k0 < HDIM; k0 += 16) {
        float4 a4 = *(const float4*)(Ag + k0);
        float4 b4 = *(const float4*)(Bg + k0);
        __syncthreads();
        stage4(As, lc, lr, a4);
        stage4(Bs, lc, lr, b4);
        __syncthreads();
        mma16f(As, Bs, acc, ty, tx);
    }
    int m0 = blockIdx.y * 64 + ty * 4, n0 = blockIdx.x * 64 + tx * 4;
#pragma unroll
    for (int i = 0; i < 4; i++) {
        float4 o = make_float4(acc[i][0] * 0.125f, acc[i][1] * 0.125f,
                               acc[i][2] * 0.125f, acc[i][3] * 0.125f);
        *(float4*)(C + (size_t)(m0 + i) * SEQ + n0) = o;
    }
}

__global__ void softmax_k() {
    float* row = g_sc + (size_t)blockIdx.x * SEQ;
    int t = threadIdx.x;
    float4 v = ((float4*)row)[t];
    __shared__ float sh[8];
    float m = fmaxf(fmaxf(v.x, v.y), fmaxf(v.z, v.w));
#pragma unroll
    for (int o = 16; o; o >>= 1) m = fmaxf(m, __shfl_xor_sync(0xFFFFFFFFu, m, o));
    if ((t & 31) == 0) sh[t >> 5] = m;
    __syncthreads();
    float bm = sh[0];
#pragma unroll
    for (int i = 1; i < 8; i++) bm = fmaxf(bm, sh[i]);
    __syncthreads();
    float e0 = fexp(v.x - bm), e1 = fexp(v.y - bm), e2 = fexp(v.z - bm), e3 = fexp(v.w - bm);
    float s = blocksum256(e0 + e1 + e2 + e3, sh);
    float inv = 1.f / s;
    ((float4*)row)[t] = make_float4(e0 * inv, e1 * inv, e2 * inv, e3 * inv);
}

__global__ void attn_av_k() {
    __shared__ __align__(16) float As[16][64];
    __shared__ __align__(16) float Bs[16][64];
    int z = blockIdx.y, b = z >> 4, h = z & 15;
    const float* A = g_sc + (size_t)z * SEQ * SEQ;
    const float* V = g_vh + (size_t)b * SEQ * DIM + h * HDIM;
    float* C = g_ao + (size_t)b * SEQ * DIM + h * HDIM;
    int tid = threadIdx.x, lr = tid >> 2, lc = (tid & 3) << 2, tx = tid & 15, ty = tid >> 4;
    int bkr = tid >> 4, bdc = (tid & 15) << 2;
    const float* Ag = A + (size_t)(blockIdx.x * 64 + lr) * SEQ + lc;
    float acc[4][4] = {};
    for (int k0 = 0; k0 < SEQ; k0 += 16) {
        float4 a4 = *(const float4*)(Ag + k0);
        float4 b4 = *(const float4*)(V + (size_t)(k0 + bkr) * DIM + bdc);
        __syncthreads();
        stage4(As, lc, lr, a4);
        *(float4*)&Bs[bkr][bdc] = b4;
        __syncthreads();
        mma16f(As, Bs, acc, ty, tx);
    }
    int m0 = blockIdx.x * 64 + ty * 4, n0 = tx * 4;
#pragma unroll
    for (int i = 0; i < 4; i++) {
        float4 o = make_float4(acc[i][0], acc[i][1], acc[i][2], acc[i][3]);
        *(float4*)(C + (size_t)(m0 + i) * DIM + n0) = o;
    }
}

// ---------------- residual + LayerNorm ----------------
__global__ void add_ln_k(const float* __restrict__ a, const float* __restrict__ r,
                         const float* __restrict__ g, const float* __restrict__ bt,
                         float* __restrict__ out) {
    int row = blockIdx.x, t = threadIdx.x;
    __shared__ float sh[8];
    float4 va = ((const float4*)(a + (size_t)row * DIM))[t];
    float4 vr = ((const float4*)(r + (size_t)row * DIM))[t];
    float v0 = va.x + vr.x, v1 = va.y + vr.y, v2 = va.z + vr.z, v3 = va.w + vr.w;
    float mean = blocksum256(v0 + v1 + v2 + v3, sh) * (1.f / DIM);
    float d0 = v0 - mean, d1 = v1 - mean, d2 = v2 - mean, d3 = v3 - mean;
    float var = blocksum256(d0 * d0 + d1 * d1 + d2 * d2 + d3 * d3, sh) * (1.f / DIM);
    float rstd = rsqrtf(var + 1e-5f);
    float4 gg = ((const float4*)g)[t], bb = ((const float4*)bt)[t];
    float4 o;
    o.x = d0 * rstd * gg.x + bb.x;
    o.y = d1 * rstd * gg.y + bb.y;
    o.z = d2 * rstd * gg.z + bb.z;
    o.w = d3 * rstd * gg.w + bb.w;
    ((float4*)(out + (size_t)row * DIM))[t] = o;
}

// ---------------- router ----------------
__global__ void router_k(const float* __restrict__ rw, const float* __restrict__ rb,
                         float* __restrict__ out_logits, float* __restrict__ out_topi) {
    int n = blockIdx.x, t = threadIdx.x;
    int e = t >> 5, lane = t & 31;
    const float* xr = g_x1 + (size_t)n * DIM;
    const float* wr = rw + (size_t)e * DIM;
    float s = 0.f;
    for (int k = lane; k < DIM; k += 32) s = fmaf(xr[k], wr[k], s);
#pragma unroll
    for (int o = 16; o; o >>= 1) s += __shfl_xor_sync(0xFFFFFFFFu, s, o);
    __shared__ float lg[8];
    if (lane == 0) lg[e] = s + rb[e];
    __syncthreads();
    if (t == 0) {
        float l[8], p[8];
        float mx = -1e30f;
#pragma unroll
        for (int q = 0; q < 8; q++) { l[q] = lg[q]; mx = fmaxf(mx, l[q]); }
        float sum = 0.f;
#pragma unroll
        for (int q = 0; q < 8; q++) { p[q] = expf(l[q] - mx); sum += p[q]; }
        float inv = 1.f / sum;
#pragma unroll
        for (int q = 0; q < 8; q++) p[q] *= inv;
        int i1 = 0; float m1 = p[0];
#pragma unroll
        for (int q = 1; q < 8; q++) if (p[q] > m1) { m1 = p[q]; i1 = q; }
        int i2 = -1; float m2 = -1.f;
#pragma unroll
        for (int q = 0; q < 8; q++) if (q != i1 && p[q] > m2) { m2 = p[q]; i2 = q; }
#pragma unroll
        for (int q = 0; q < 8; q++) g_logits[n * 8 + q] = l[q];
        g_ti[n * 2] = i1;  g_ti[n * 2 + 1] = i2;
        g_tv[n * 2] = m1;  g_tv[n * 2 + 1] = m2;
        if (out_logits) {
#pragma unroll
            for (int q = 0; q < 8; q++) out_logits[n * 8 + q] = l[q];
        }
        if (out_topi) { out_topi[n * 2] = (float)i1; out_topi[n * 2 + 1] = (float)i2; }
    }
}

// ---------------- capacity selection ----------------
__global__ void cap_select_k() {
    int e = blockIdx.x, t = threadIdx.x;
    __shared__ unsigned long long keys[NTOK];
    __shared__ int s_cnt;
    if (t == 0) s_cnt = 0;
    __syncthreads();
    int local = 0;
    for (int n = t; n < NTOK; n += 1024) {
        bool cand = (g_ti[n * 2] == e) || (g_ti[n * 2 + 1] == e);
        float v = cand ? g_logits[n * NEXP + e] : NEGV;
        unsigned u = __float_as_uint(v);
        u = (u & 0x80000000u) ? ~u : (u | 0x80000000u);
        unsigned long long key = ((unsigned long long)u << 32) | (unsigned)(0xFFFFFFFFu - (unsigned)n);
        keys[n] = ~key;
        local += cand ? 1 : 0;
    }
    atomicAdd(&s_cnt, local);
    __syncthreads();
    for (int k = 2; k <= NTOK; k <<= 1)
        for (int j = k >> 1; j > 0; j >>= 1) {
            for (int base = t; base < NTOK; base += 1024) {
                int l = base ^ j;
                if (l > base) {
                    bool up = ((base & k) == 0);
                    unsigned long long a = keys[base], b = keys[l];
                    if ((a > b) == up) { keys[base] = b; keys[l] = a; }
                }
            }
            __syncthreads();
        }
    int cnt = min(s_cnt, CAPN);
    if (t == 0) g_cnt[e] = cnt;
    for (int c = t; c < CAPN; c += 1024) {
        if (c < cnt) {
            unsigned long long key = ~keys[c];
            int tok = (int)(0xFFFFFFFFu - (unsigned)(key & 0xFFFFFFFFu));
            g_tok[e * CAPN + c] = tok;
            g_w[e * CAPN + c] = (g_ti[tok * 2] == e) ? g_tv[tok * 2] : g_tv[tok * 2 + 1];
        } else {
            g_tok[e * CAPN + c] = 0;
            g_w[e * CAPN + c] = 0.f;
        }
    }
}

__global__ void zero_moe_k() {
    size_t i = (size_t)blockIdx.x * blockDim.x + threadIdx.x;
    ((float4*)g_moe)[i] = make_float4(0.f, 0.f, 0.f, 0.f);
}

// ---------------- host ----------------
extern "C" void kernel_launch(void* const* d_in, const int* in_sizes, int n_in,
                              void* d_out, int out_size) {
    const float* x   = (const float*)d_in[0];
    const float* ipw = (const float*)d_in[1];
    const float* ipb = (const float*)d_in[2];
    const float* opw = (const float*)d_in[3];
    const float* opb = (const float*)d_in[4];
    const float* n1g = (const float*)d_in[5];
    const float* n1b = (const float*)d_in[6];
    const float* n2g = (const float*)d_in[7];
    const float* n2b = (const float*)d_in[8];
    const float* rw  = (const float*)d_in[9];
    const float* rb  = (const float*)d_in[10];
    const float* gw  = (const float*)d_in[11];
    const float* gb  = (const float*)d_in[12];
    const float* vw  = (const float*)d_in[13];
    const float* vb  = (const float*)d_in[14];
    const float* wow = (const float*)d_in[15];
    const float* wob = (const float*)d_in[16];
    float* out = (float*)d_out;

    const int SM_G128 = 65536;
    const int SM_GV   = 66560;
    cudaFuncSetAttribute(gemm_mma,      cudaFuncAttributeMaxDynamicSharedMemorySize, SM_G128);
    cudaFuncSetAttribute(moe_gatval_mma, cudaFuncAttributeMaxDynamicSharedMemorySize, SM_GV);
    cudaFuncSetAttribute(moe_wo_mma,    cudaFuncAttributeMaxDynamicSharedMemorySize, SM_G128);

    static cudaStream_t s2 = nullptr;
    static cudaEvent_t ev0 = nullptr, ev2 = nullptr;
    if (!s2) {
        cudaStreamCreateWithFlags(&s2, cudaStreamNonBlocking);
        cudaEventCreateWithFlags(&ev0, cudaEventDisableTiming);
        cudaEventCreateWithFlags(&ev2, cudaEventDisableTiming);
    }

    void *p_qkv, *p_qh, *p_kh, *p_vh, *p_ao, *p_tmp, *p_x1, *p_moe, *p_sc;
    void *p_xc, *p_wipc, *p_qc, *p_kc, *p_vc, *p_aoc, *p_wopc;
    void *p_x1c, *p_gwc, *p_vwc, *p_woc, *p_hc;
    cudaGetSymbolAddress(&p_qkv, g_qkv);  cudaGetSymbolAddress(&p_qh, g_qh);
    cudaGetSymbolAddress(&p_kh, g_kh);    cudaGetSymbolAddress(&p_vh, g_vh);
    cudaGetSymbolAddress(&p_ao, g_ao);    cudaGetSymbolAddress(&p_tmp, g_tmp);
    cudaGetSymbolAddress(&p_x1, g_x1);    cudaGetSymbolAddress(&p_moe, g_moe);
    cudaGetSymbolAddress(&p_sc, g_sc);
    cudaGetSymbolAddress(&p_xc, g_xc);    cudaGetSymbolAddress(&p_wipc, g_wipc);
    cudaGetSymbolAddress(&p_qc, g_qc);    cudaGetSymbolAddress(&p_kc, g_kc);
    cudaGetSymbolAddress(&p_vc, g_vc);
    cudaGetSymbolAddress(&p_aoc, g_aoc);  cudaGetSymbolAddress(&p_wopc, g_wopc);
    cudaGetSymbolAddress(&p_x1c, g_x1c);
    cudaGetSymbolAddress(&p_gwc, g_gwc);  cudaGetSymbolAddress(&p_vwc, g_vwc);
    cudaGetSymbolAddress(&p_woc, g_woc);  cudaGetSymbolAddress(&p_hc, g_hc);

    float* out_logits = (out_size >= NTOK * DIM + NTOK * NEXP) ? out + NTOK * DIM : nullptr;
    float* out_topi   = (out_size >= NTOK * DIM + NTOK * NEXP + NTOK * 2)
                            ? out + NTOK * DIM + NTOK * NEXP : nullptr;

    // ---- fork: bulk MoE weight conversions overlap the attention phase ----
    cudaEventRecord(ev0, 0);
    cudaStreamWaitEvent(s2, ev0, 0);
    conv3_k<<<(long)NEXP * FF * DIM / 256, 256, 0, s2>>>(gw, DIM, (__nv_bfloat16*)p_gwc, 10, 1, (long)NEXP * FF * DIM);
    conv3_k<<<(long)NEXP * FF * DIM / 256, 256, 0, s2>>>(vw, DIM, (__nv_bfloat16*)p_vwc, 10, 1, (long)NEXP * FF * DIM);
    conv3_k<<<(long)NEXP * DIM * FF / 256, 256, 0, s2>>>(wow, FF, (__nv_bfloat16*)p_woc, 12, 1, (long)NEXP * DIM * FF);
    cudaEventRecord(ev2, s2);

    zero_moe_k<<<NTOK * DIM / 4 / 256, 256>>>();
    rope_tables_k<<<(SEQ * 32 + 255) / 256, 256>>>();

    // ---- attention: projections in 3-term bf16, core attention fp32 ----
    conv3_k<<<(long)NTOK * DIM / 256, 256>>>(x, DIM, (__nv_bfloat16*)p_xc, 10, 0, (long)NTOK * DIM);
    conv3_k<<<(long)D3 * DIM / 256, 256>>>(ipw, DIM, (__nv_bfloat16*)p_wipc, 10, 1, (long)D3 * DIM);
    gemm_mma<<<dim3(32, 24, 1), 128, SM_G128>>>(
        (__nv_bfloat16*)p_xc, 3072, 0, (__nv_bfloat16*)p_wipc, 3072, 0,
        ipb, 1.f, (float*)p_qkv, D3, 1, 0, 0, 3072);
    rope_apply_k<<<(2 * NTOK * NH * 32) / 256, 256>>>();

    conv3_k<<<(long)NTOK * DIM / 256, 256>>>((float*)p_qkv,           D3, (__nv_bfloat16*)p_qc, 10, 0, (long)NTOK * DIM);
    conv3_k<<<(long)NTOK * DIM / 256, 256>>>((float*)p_qkv + DIM,     D3, (__nv_bfloat16*)p_kc, 10, 0, (long)NTOK * DIM);
    conv3_k<<<(long)NTOK * DIM / 256, 256>>>((float*)p_qkv + 2 * DIM, D3, (__nv_bfloat16*)p_vc, 10, 0, (long)NTOK * DIM);
    gemm_mma<<<dim3(32, 8, 1), 128, SM_G128>>>(
        (__nv_bfloat16*)p_qc, 3072, 0, (__nv_bfloat16*)p_wipc, 3072, 0,
        ipb, 1.f, (float*)p_qh, DIM, 1, 0, 0, 3072);
    gemm_mma<<<dim3(32, 8, 1), 128, SM_G128>>>(
        (__nv_bfloat16*)p_kc, 3072, 0, (__nv_bfloat16*)p_wipc + (long)DIM * 3072, 3072, 0,
        ipb + DIM, 1.f, (float*)p_kh, DIM, 1, 0, 0, 3072);
    gemm_mma<<<dim3(32, 8, 1), 128, SM_G128>>>(
        (__nv_bfloat16*)p_vc, 3072, 0, (__nv_bfloat16*)p_wipc + 2L * DIM * 3072, 3072, 0,
        ipb + 2 * DIM, 1.f, (float*)p_vh, DIM, 1, 0, 0, 3072);

    attn_scores_k<<<dim3(SEQ / 64, SEQ / 64, 4 * NH), 256>>>();
    softmax_k<<<4 * NH * SEQ, 256>>>();
    attn_av_k<<<dim3(SEQ / 64, 4 * NH), 256>>>();

    conv3_k<<<(long)NTOK * DIM / 256, 256>>>((float*)p_ao, DIM, (__nv_bfloat16*)p_aoc, 10, 0, (long)NTOK * DIM);
    conv3_k<<<(long)DIM * DIM / 256, 256>>>(opw, DIM, (__nv_bfloat16*)p_wopc, 10, 1, (long)DIM * DIM);
    gemm_mma<<<dim3(32, 8, 1), 128, SM_G128>>>(
        (__nv_bfloat16*)p_aoc, 3072, 0, (__nv_bfloat16*)p_wopc, 3072, 0,
        opb, 1.f, (float*)p_tmp, DIM, 1, 0, 0, 3072);
    add_ln_k<<<NTOK, 256>>>(x, (float*)p_tmp, n1g, n1b, (float*)p_x1);

    // ---- router + capacity ----
    router_k<<<NTOK, 256>>>(rw, rb, out_logits, out_topi);
    cap_select_k<<<NEXP, 1024>>>();

    // ---- MoE ----
    conv3_k<<<(long)NTOK * DIM / 256, 256>>>((float*)p_x1, DIM, (__nv_bfloat16*)p_x1c, 10, 0, (long)NTOK * DIM);
    cudaStreamWaitEvent(0, ev2, 0);
    moe_gatval_mma<<<dim3(16, 64, 8), 128, SM_GV>>>(gb, vb, (float*)p_sc);
    conv3_k<<<(long)NEXP * CAPN * FF / 256, 256>>>((float*)p_sc, FF, (__nv_bfloat16*)p_hc, 12, 0, (long)NEXP * CAPN * FF);
    moe_wo_mma<<<dim3(16, 8, 8), 128, SM_G128>>>(wob);

    add_ln_k<<<NTOK, 256>>>((float*)p_x1, (float*)p_moe, n2g, n2b, out);
}

// round 17
// speedup vs baseline: 1.1993x; 1.1993x over previous
#include <cuda_runtime.h>
#include <cuda_bf16.h>
#include <math.h>
#include <stdint.h>

#define NTOK 4096
#define DIM  1024
#define D3   3072
#define NH   16
#define HDIM 64
#define SEQ  1024
#define FF   4096
#define NEXP 8
#define CAPN 2048
#define NEGV -1e30f

// ---------------- device scratch ----------------
__device__ float g_qkv[12582912];
__device__ float g_qh [4194304];
__device__ float g_kh [4194304];
__device__ float g_vh [4194304];
__device__ float g_sc [67108864];          // scores; later reused as MoE h [8,2048,4096]
__device__ float g_ao [4194304];
__device__ float g_tmp[4194304];
__device__ float g_x1 [4194304];
__device__ float g_logits[NTOK * NEXP];
__device__ float g_tv[NTOK * 2];
__device__ int   g_ti[NTOK * 2];
__device__ int   g_tok[NEXP * CAPN];
__device__ float g_w  [NEXP * CAPN];
__device__ int   g_cnt[NEXP];
__device__ float g_moe[4194304];
__device__ float g_cos[SEQ * 32];
__device__ float g_sin[SEQ * 32];
// 3-term split buffers (attention projection GEMMs)
__device__ __nv_bfloat16 g_xc  [12582912];
__device__ __nv_bfloat16 g_wipc[ 9437184];
__device__ __nv_bfloat16 g_qc  [12582912];
__device__ __nv_bfloat16 g_kc  [12582912];
__device__ __nv_bfloat16 g_vc  [12582912];
__device__ __nv_bfloat16 g_aoc [12582912];
__device__ __nv_bfloat16 g_wopc[ 3145728];
// 2-term split buffers (MoE path): act=[h|l], wgt=[h|h]
__device__ __nv_bfloat16 g_x1c [ 8388608];   // [4096,2048]
__device__ __nv_bfloat16 g_gwc [67108864];   // [8*4096,2048]
__device__ __nv_bfloat16 g_vwc [67108864];
__device__ __nv_bfloat16 g_woc [67108864];   // [8*1024,8192]
__device__ __nv_bfloat16 g_hc  [134217728];  // [8*2048,8192]

// ---------------- helpers ----------------
__device__ __forceinline__ uint32_t smem_u32(const void* p) {
    uint32_t a;
    asm("{ .reg .u64 t; cvta.to.shared.u64 t, %1; cvt.u32.u64 %0, t; }" : "=r"(a) : "l"(p));
    return a;
}
#define SWZ128(o) ((o) ^ (((o) >> 3) & 0x70))
#define LDSM4(r0, r1, r2, r3, addr) \
    asm volatile("ldmatrix.sync.aligned.m8n8.x4.shared.b16 {%0,%1,%2,%3}, [%4];" \
        : "=r"(r0), "=r"(r1), "=r"(r2), "=r"(r3) : "r"(addr))
#define MMA16816(d, a, b) \
    asm volatile("mma.sync.aligned.m16n8k16.row.col.f32.bf16.bf16.f32 " \
        "{%0,%1,%2,%3}, {%4,%5,%6,%7}, {%8,%9}, {%0,%1,%2,%3};" \
        : "+f"((d)[0]), "+f"((d)[1]), "+f"((d)[2]), "+f"((d)[3]) \
        : "r"((a)[0]), "r"((a)[1]), "r"((a)[2]), "r"((a)[3]), "r"((b)[0]), "r"((b)[1]))
#define CP_ASYNC16(dst, src) \
    asm volatile("cp.async.cg.shared.global [%0], [%1], 16;" :: "r"(dst), "l"(src))
#define CP_COMMIT() asm volatile("cp.async.commit_group;")
#define CP_WAIT0()  asm volatile("cp.async.wait_group 0;")

__device__ __forceinline__ void split_bf16(float v, __nv_bfloat16& h, __nv_bfloat16& l) {
    h = __float2bfloat16(v);
    l = __float2bfloat16(v - __bfloat162float(h));
}

// FMA-only exp (no MUFU), max rel err ~2e-6
__device__ __forceinline__ float fexp(float x) {
    x = fminf(fmaxf(x, -87.0f), 87.0f);
    float t = x * 1.4426950408889634f;
    float n = floorf(t);
    float f = t - n;
    float p = 1.3333558146428443e-3f;
    p = fmaf(p, f, 9.6181291076284772e-3f);
    p = fmaf(p, f, 5.5504108664821580e-2f);
    p = fmaf(p, f, 2.4022650695910072e-1f);
    p = fmaf(p, f, 6.9314718055994531e-1f);
    p = fmaf(p, f, 1.0f);
    float s = __int_as_float(((int)n + 127) << 23);
    return p * s;
}

__device__ __forceinline__ float blocksum256(float v, float* sh) {
    int t = threadIdx.x;
#pragma unroll
    for (int o = 16; o; o >>= 1) v += __shfl_xor_sync(0xFFFFFFFFu, v, o);
    __syncthreads();
    if ((t & 31) == 0) sh[t >> 5] = v;
    __syncthreads();
    float tot = 0.f;
#pragma unroll
    for (int i = 0; i < 8; i++) tot += sh[i];
    return tot;
}

// ============ warp-MMA GEMM: 128x128 block, 4 warps (64x64 warp tile) ============
__global__ void __launch_bounds__(128, 2) gemm_mma(
    const __nv_bfloat16* __restrict__ A, long lda, long szA,
    const __nv_bfloat16* __restrict__ B, long ldb, long szB,
    const float* __restrict__ bias, float scale,
    float* __restrict__ C, long ldc, int zdiv, long szC1, long szC2, int K3)
{
    extern __shared__ char sm[];
    char* sA = sm;
    char* sB = sm + 32768;
    const int tid = threadIdx.x, w = tid >> 5, lane = tid & 31;
    const int wm = (w & 1) * 64, wn = (w >> 1) * 64;

    const long z = blockIdx.z;
    const __nv_bfloat16* Az = A + z * szA + (long)(blockIdx.x * 128) * lda;
    const __nv_bfloat16* Bz = B + z * szB + (long)(blockIdx.y * 128) * ldb;
    const int nchunk = K3 >> 6;
    uint32_t sAu = smem_u32(sA), sBu = smem_u32(sB);

#define CPA(s, c) { _Pragma("unroll") for (int i = 0; i < 8; i++) { \
        int idx = tid + i * 128, r = idx >> 3, cc = idx & 7; \
        CP_ASYNC16(sAu + (s) * 16384 + SWZ128(r * 128 + cc * 16), \
                   Az + (long)r * lda + (c) * 64 + cc * 8); } \
    _Pragma("unroll") for (int i = 0; i < 8; i++) { \
        int idx = tid + i * 128, r = idx >> 3, cc = idx & 7; \
        CP_ASYNC16(sBu + (s) * 16384 + SWZ128(r * 128 + cc * 16), \
                   Bz + (long)r * ldb + (c) * 64 + cc * 8); } }

    float acc[4][8][4] = {};
    CPA(0, 0); CP_COMMIT();
    CP_WAIT0(); __syncthreads();

    for (int c = 0; c < nchunk; c++) {
        if (c + 1 < nchunk) { CPA((c + 1) & 1, c + 1); CP_COMMIT(); }
        char* a0 = sA + (c & 1) * 16384;
        char* b0 = sB + (c & 1) * 16384;
#pragma unroll
        for (int ks = 0; ks < 4; ks++) {
            uint32_t af[4][4];
#pragma unroll
            for (int mi = 0; mi < 4; mi++) {
                uint32_t ad = smem_u32(a0 + SWZ128((wm + mi * 16 + (lane & 15)) * 128 +
                                                   ks * 32 + (lane >> 4) * 16));
                LDSM4(af[mi][0], af[mi][1], af[mi][2], af[mi][3], ad);
            }
            uint32_t bf[8][2];
#pragma unroll
            for (int j = 0; j < 4; j++) {
                uint32_t r0, r1, r2, r3;
                uint32_t bd = smem_u32(b0 + SWZ128((wn + j * 16 + (lane & 15)) * 128 +
                                                   ks * 32 + (lane >> 4) * 16));
                LDSM4(r0, r1, r2, r3, bd);
                bf[2 * j][0] = r0; bf[2 * j][1] = r2;
                bf[2 * j + 1][0] = r1; bf[2 * j + 1][1] = r3;
            }
#pragma unroll
            for (int mi = 0; mi < 4; mi++)
#pragma unroll
                for (int nj = 0; nj < 8; nj++)
                    MMA16816(acc[mi][nj], af[mi], bf[nj]);
        }
        if (c + 1 < nchunk) CP_WAIT0();
        __syncthreads();
    }
#undef CPA

    long coff = (long)(z / zdiv) * szC1 + (long)(z % zdiv) * szC2;
    int m0 = blockIdx.x * 128 + wm + (lane >> 2);
    int nb = blockIdx.y * 128 + wn + (lane & 3) * 2;
#pragma unroll
    for (int mi = 0; mi < 4; mi++) {
        float* rp0 = C + coff + (long)(m0 + mi * 16) * ldc;
        float* rp1 = rp0 + 8 * ldc;
#pragma unroll
        for (int nj = 0; nj < 8; nj++) {
            int n = nb + nj * 8;
            float b0v = 0.f, b1v = 0.f;
            if (bias) { b0v = bias[n]; b1v = bias[n + 1]; }
            float2 o0 = make_float2(acc[mi][nj][0] * scale + b0v, acc[mi][nj][1] * scale + b1v);
            float2 o1 = make_float2(acc[mi][nj][2] * scale + b0v, acc[mi][nj][3] * scale + b1v);
            *(float2*)(rp0 + n) = o0;
            *(float2*)(rp1 + n) = o1;
        }
    }
}

// ============ fused MoE gate+val GEMMs + silu, fp32 h out (2-term, K=2048) ============
__global__ void __launch_bounds__(128, 2) moe_gatval_mma(
    const float* __restrict__ gb, const float* __restrict__ vb, float* __restrict__ Hout)
{
    extern __shared__ char sm[];
    char* sA = sm;
    char* sG = sm + 32768;
    char* sV = sm + 49152;
    int* s_tok = (int*)(sm + 65536);
    const int e = blockIdx.z, bm = blockIdx.x * 128;
    if (bm >= g_cnt[e]) return;
    const int tid = threadIdx.x, w = tid >> 5, lane = tid & 31;
    const int wm = (w & 1) * 64, wn = (w >> 1) * 32;

    s_tok[tid] = g_tok[e * CAPN + bm + tid];
    __syncthreads();

    const __nv_bfloat16* Bg = g_gwc + (long)e * FF * 2048 + (long)(blockIdx.y * 64) * 2048;
    const __nv_bfloat16* Bv = g_vwc + (long)e * FF * 2048 + (long)(blockIdx.y * 64) * 2048;
    uint32_t sAu = smem_u32(sA), sGu = smem_u32(sG), sVu = smem_u32(sV);

#define CPA(s, c) { _Pragma("unroll") for (int i = 0; i < 8; i++) { \
        int idx = tid + i * 128, r = idx >> 3, cc = idx & 7; \
        CP_ASYNC16(sAu + (s) * 16384 + SWZ128(r * 128 + cc * 16), \
                   g_x1c + (long)s_tok[r] * 2048 + (c) * 64 + cc * 8); } \
    _Pragma("unroll") for (int i = 0; i < 4; i++) { \
        int idx = tid + i * 128, r = idx >> 3, cc = idx & 7; \
        CP_ASYNC16(sGu + (s) * 8192 + SWZ128(r * 128 + cc * 16), \
                   Bg + (long)r * 2048 + (c) * 64 + cc * 8); \
        CP_ASYNC16(sVu + (s) * 8192 + SWZ128(r * 128 + cc * 16), \
                   Bv + (long)r * 2048 + (c) * 64 + cc * 8); } }

    float ag[4][4][4] = {}, av[4][4][4] = {};
    CPA(0, 0); CP_COMMIT();
    CP_WAIT0(); __syncthreads();

    for (int c = 0; c < 32; c++) {
        if (c + 1 < 32) { CPA((c + 1) & 1, c + 1); CP_COMMIT(); }
        char* a0 = sA + (c & 1) * 16384;
        char* gg0 = sG + (c & 1) * 8192;
        char* vv0 = sV + (c & 1) * 8192;
#pragma unroll
        for (int ks = 0; ks < 4; ks++) {
            uint32_t af[4][4];
#pragma unroll
            for (int mi = 0; mi < 4; mi++) {
                uint32_t ad = smem_u32(a0 + SWZ128((wm + mi * 16 + (lane & 15)) * 128 +
                                                   ks * 32 + (lane >> 4) * 16));
                LDSM4(af[mi][0], af[mi][1], af[mi][2], af[mi][3], ad);
            }
            uint32_t gf[4][2], vf[4][2];
#pragma unroll
            for (int j = 0; j < 2; j++) {
                uint32_t r0, r1, r2, r3;
                uint32_t gd = smem_u32(gg0 + SWZ128((wn + j * 16 + (lane & 15)) * 128 +
                                                    ks * 32 + (lane >> 4) * 16));
                LDSM4(r0, r1, r2, r3, gd);
                gf[2 * j][0] = r0; gf[2 * j][1] = r2;
                gf[2 * j + 1][0] = r1; gf[2 * j + 1][1] = r3;
                uint32_t vd = smem_u32(vv0 + SWZ128((wn + j * 16 + (lane & 15)) * 128 +
                                                    ks * 32 + (lane >> 4) * 16));
                LDSM4(r0, r1, r2, r3, vd);
                vf[2 * j][0] = r0; vf[2 * j][1] = r2;
                vf[2 * j + 1][0] = r1; vf[2 * j + 1][1] = r3;
            }
#pragma unroll
            for (int mi = 0; mi < 4; mi++)
#pragma unroll
                for (int nj = 0; nj < 4; nj++) {
                    MMA16816(ag[mi][nj], af[mi], gf[nj]);
                    MMA16816(av[mi][nj], af[mi], vf[nj]);
                }
        }
        if (c + 1 < 32) CP_WAIT0();
        __syncthreads();
    }
#undef CPA

    int m0 = bm + wm + (lane >> 2);
    int nb = blockIdx.y * 64 + wn + (lane & 3) * 2;
#pragma unroll
    for (int mi = 0; mi < 4; mi++) {
#pragma unroll
        for (int nj = 0; nj < 4; nj++) {
            int n = nb + nj * 8;
            float gb0 = gb[e * FF + n], gb1 = gb[e * FF + n + 1];
            float vb0 = vb[e * FF + n], vb1 = vb[e * FF + n + 1];
#pragma unroll
            for (int half = 0; half < 2; half++) {
                int m = m0 + mi * 16 + half * 8;
                float gt0 = ag[mi][nj][half * 2]     + gb0;
                float gt1 = ag[mi][nj][half * 2 + 1] + gb1;
                float vl0 = av[mi][nj][half * 2]     + vb0;
                float vl1 = av[mi][nj][half * 2 + 1] + vb1;
                float h0 = vl0 * (gt0 / (1.f + fexp(-gt0)));
                float h1 = vl1 * (gt1 / (1.f + fexp(-gt1)));
                float* dst = Hout + ((long)e * CAPN + m) * FF + n;
                dst[0] = h0; dst[1] = h1;
            }
        }
    }
}

// ============ MoE wo GEMM + weighted atomic scatter (2-term, K=8192) ============
__global__ void __launch_bounds__(128, 2) moe_wo_mma(const float* __restrict__ wob)
{
    extern __shared__ char sm[];
    char* sA = sm;
    char* sB = sm + 32768;
    const int e = blockIdx.z, bm = blockIdx.x * 128;
    const int cnt = g_cnt[e];
    if (bm >= cnt) return;
    const int tid = threadIdx.x, w = tid >> 5, lane = tid & 31;
    const int wm = (w & 1) * 64, wn = (w >> 1) * 64;

    const __nv_bfloat16* Az = g_hc + ((long)e * CAPN + bm) * 8192;
    const __nv_bfloat16* Bz = g_woc + (long)e * DIM * 8192 + (long)(blockIdx.y * 128) * 8192;
    uint32_t sAu = smem_u32(sA), sBu = smem_u32(sB);

#define CPA(s, c) { _Pragma("unroll") for (int i = 0; i < 8; i++) { \
        int idx = tid + i * 128, r = idx >> 3, cc = idx & 7; \
        CP_ASYNC16(sAu + (s) * 16384 + SWZ128(r * 128 + cc * 16), \
                   Az + (long)r * 8192 + (c) * 64 + cc * 8); \
        CP_ASYNC16(sBu + (s) * 16384 + SWZ128(r * 128 + cc * 16), \
                   Bz + (long)r * 8192 + (c) * 64 + cc * 8); } }

    float acc[4][8][4] = {};
    CPA(0, 0); CP_COMMIT();
    CP_WAIT0(); __syncthreads();

    for (int c = 0; c < 128; c++) {
        if (c + 1 < 128) { CPA((c + 1) & 1, c + 1); CP_COMMIT(); }
        char* a0 = sA + (c & 1) * 16384;
        char* b0 = sB + (c & 1) * 16384;
#pragma unroll
        for (int ks = 0; ks < 4; ks++) {
            uint32_t af[4][4];
#pragma unroll
            for (int mi = 0; mi < 4; mi++) {
                uint32_t ad = smem_u32(a0 + SWZ128((wm + mi * 16 + (lane & 15)) * 128 +
                                                   ks * 32 + (lane >> 4) * 16));
                LDSM4(af[mi][0], af[mi][1], af[mi][2], af[mi][3], ad);
            }
            uint32_t bfr[8][2];
#pragma unroll
            for (int j = 0; j < 4; j++) {
                uint32_t r0, r1, r2, r3;
                uint32_t bd = smem_u32(b0 + SWZ128((wn + j * 16 + (lane & 15)) * 128 +
                                                   ks * 32 + (lane >> 4) * 16));
                LDSM4(r0, r1, r2, r3, bd);
                bfr[2 * j][0] = r0; bfr[2 * j][1] = r2;
                bfr[2 * j + 1][0] = r1; bfr[2 * j + 1][1] = r3;
            }
#pragma unroll
            for (int mi = 0; mi < 4; mi++)
#pragma unroll
                for (int nj = 0; nj < 8; nj++)
                    MMA16816(acc[mi][nj], af[mi], bfr[nj]);
        }
        if (c + 1 < 128) CP_WAIT0();
        __syncthreads();
    }
#undef CPA

    int m0 = bm + wm + (lane >> 2);
    int nb = blockIdx.y * 128 + wn + (lane & 3) * 2;
#pragma unroll
    for (int mi = 0; mi < 4; mi++) {
#pragma unroll
        for (int half = 0; half < 2; half++) {
            int m = m0 + mi * 16 + half * 8;
            if (m < cnt) {
                int tok = g_tok[e * CAPN + m];
                float wt = g_w[e * CAPN + m];
                float* dst = g_moe + (long)tok * DIM;
#pragma unroll
                for (int nj = 0; nj < 8; nj++) {
                    int n = nb + nj * 8;
                    atomicAdd(dst + n,     (acc[mi][nj][half * 2]     + wob[e * DIM + n])     * wt);
                    atomicAdd(dst + n + 1, (acc[mi][nj][half * 2 + 1] + wob[e * DIM + n + 1]) * wt);
                }
            }
        }
    }
}

// ---------------- conversions ----------------
// 3-term: act [h|h|l] (patB=0), wgt [h|l|h] (patB=1)  — attention path
__global__ void conv3_k(const float* __restrict__ src, long ldsrc,
                        __nv_bfloat16* __restrict__ dst, int kshift, int patB, long total) {
    long idx = (long)blockIdx.x * 256 + threadIdx.x;
    if (idx >= total) return;
    long K = 1L << kshift;
    long r = idx >> kshift;
    int k = (int)(idx & (K - 1));
    float v = src[r * ldsrc + k];
    __nv_bfloat16 h, l; split_bf16(v, h, l);
    __nv_bfloat16* d = dst + r * (3L << kshift) + k;
    d[0] = h; d[K] = patB ? l : h; d[2 * K] = patB ? h : l;
}

// 2-term: act [h|l] (wgt=0), wgt [h|h] (wgt=1)  — MoE path
__global__ void conv2_k(const float* __restrict__ src, long ldsrc,
                        __nv_bfloat16* __restrict__ dst, int kshift, int wgt, long total) {
    long idx = (long)blockIdx.x * 256 + threadIdx.x;
    if (idx >= total) return;
    long K = 1L << kshift;
    long r = idx >> kshift;
    int k = (int)(idx & (K - 1));
    float v = src[r * ldsrc + k];
    __nv_bfloat16 h, l; split_bf16(v, h, l);
    __nv_bfloat16* d = dst + r * (2L << kshift) + k;
    d[0] = h; d[K] = wgt ? h : l;
}

// ---------------- RoPE ----------------
__global__ void rope_tables_k() {
    int idx = blockIdx.x * blockDim.x + threadIdx.x;
    if (idx >= SEQ * 32) return;
    int s = idx >> 5, i = idx & 31;
    float inv = powf(10000.f, -(float)i / 32.f);
    float ang = (float)s * inv;
    g_cos[idx] = (float)cos((double)ang);
    g_sin[idx] = (float)sin((double)ang);
}

__global__ void rope_apply_k() {
    int gid = blockIdx.x * blockDim.x + threadIdx.x;
    int i = gid & 31;
    int h = (gid >> 5) & 15;
    int n = (gid >> 9) & (NTOK - 1);
    int t = gid >> 21;
    int s = n & (SEQ - 1);
    float c = g_cos[s * 32 + i], sn = g_sin[s * 32 + i];
    float* base = g_qkv + (size_t)n * D3 + t * DIM + h * HDIM;
    float x1v = base[i], x2v = base[i + 32];
    base[i]      = x1v * c - x2v * sn;
    base[i + 32] = x2v * c + x1v * sn;
}

// ---------------- attention fp32 (R1 certified) ----------------
__device__ __forceinline__ void stage4(float S[16][64], int lc, int lr, float4 v) {
    S[lc + 0][lr] = v.x; S[lc + 1][lr] = v.y; S[lc + 2][lr] = v.z; S[lc + 3][lr] = v.w;
}
__device__ __forceinline__ void mma16f(float A[16][64], float B[16][64],
                                       float acc[4][4], int ty, int tx) {
#pragma unroll
    for (int kk = 0; kk < 16; kk++) {
        float4 a = *(const float4*)&A[kk][ty * 4];
        float4 b = *(const float4*)&B[kk][tx * 4];
        float av[4] = {a.x, a.y, a.z, a.w};
        float bv[4] = {b.x, b.y, b.z, b.w};
#pragma unroll
        for (int i = 0; i < 4; i++)
#pragma unroll
            for (int j = 0; j < 4; j++)
                acc[i][j] = fmaf(av[i], bv[j], acc[i][j]);
    }
}

__global__ void attn_scores_k() {
    __shared__ __align__(16) float As[16][64];
    __shared__ __align__(16) float Bs[16][64];
    int z = blockIdx.z, b = z >> 4, h = z & 15;
    const float* Abase = g_qh + (size_t)b * SEQ * DIM + h * HDIM;
    const float* Bbase = g_kh + (size_t)b * SEQ * DIM + h * HDIM;
    float* C = g_sc + (size_t)z * SEQ * SEQ;
    int tid = threadIdx.x, lr = tid >> 2, lc = (tid & 3) << 2, tx = tid & 15, ty = tid >> 4;
    const float* Ag = Abase + (size_t)(blockIdx.y * 64 + lr) * DIM + lc;
    const float* Bg = Bbase + (size_t)(blockIdx.x * 64 + lr) * DIM + lc;
    float acc[4][4] = {};
#pragma unroll
    for (int k0 = 0; k0 < HDIM; k0 += 16) {
        float4 a4 = *(const float4*)(Ag + k0);
        float4 b4 = *(const float4*)(Bg + k0);
        __syncthreads();
        stage4(As, lc, lr, a4);
        stage4(Bs, lc, lr, b4);
        __syncthreads();
        mma16f(As, Bs, acc, ty, tx);
    }
    int m0 = blockIdx.y * 64 + ty * 4, n0 = blockIdx.x * 64 + tx * 4;
#pragma unroll
    for (int i = 0; i < 4; i++) {
        float4 o = make_float4(acc[i][0] * 0.125f, acc[i][1] * 0.125f,
                               acc[i][2] * 0.125f, acc[i][3] * 0.125f);
        *(float4*)(C + (size_t)(m0 + i) * SEQ + n0) = o;
    }
}

__global__ void softmax_k() {
    float* row = g_sc + (size_t)blockIdx.x * SEQ;
    int t = threadIdx.x;
    float4 v = ((float4*)row)[t];
    __shared__ float sh[8];
    float m = fmaxf(fmaxf(v.x, v.y), fmaxf(v.z, v.w));
#pragma unroll
    for (int o = 16; o; o >>= 1) m = fmaxf(m, __shfl_xor_sync(0xFFFFFFFFu, m, o));
    if ((t & 31) == 0) sh[t >> 5] = m;
    __syncthreads();
    float bm = sh[0];
#pragma unroll
    for (int i = 1; i < 8; i++) bm = fmaxf(bm, sh[i]);
    __syncthreads();
    float e0 = fexp(v.x - bm), e1 = fexp(v.y - bm), e2 = fexp(v.z - bm), e3 = fexp(v.w - bm);
    float s = blocksum256(e0 + e1 + e2 + e3, sh);
    float inv = 1.f / s;
    ((float4*)row)[t] = make_float4(e0 * inv, e1 * inv, e2 * inv, e3 * inv);
}

__global__ void attn_av_k() {
    __shared__ __align__(16) float As[16][64];
    __shared__ __align__(16) float Bs[16][64];
    int z = blockIdx.y, b = z >> 4, h = z & 15;
    const float* A = g_sc + (size_t)z * SEQ * SEQ;
    const float* V = g_vh + (size_t)b * SEQ * DIM + h * HDIM;
    float* C = g_ao + (size_t)b * SEQ * DIM + h * HDIM;
    int tid = threadIdx.x, lr = tid >> 2, lc = (tid & 3) << 2, tx = tid & 15, ty = tid >> 4;
    int bkr = tid >> 4, bdc = (tid & 15) << 2;
    const float* Ag = A + (size_t)(blockIdx.x * 64 + lr) * SEQ + lc;
    float acc[4][4] = {};
    for (int k0 = 0; k0 < SEQ; k0 += 16) {
        float4 a4 = *(const float4*)(Ag + k0);
        float4 b4 = *(const float4*)(V + (size_t)(k0 + bkr) * DIM + bdc);
        __syncthreads();
        stage4(As, lc, lr, a4);
        *(float4*)&Bs[bkr][bdc] = b4;
        __syncthreads();
        mma16f(As, Bs, acc, ty, tx);
    }
    int m0 = blockIdx.x * 64 + ty * 4, n0 = tx * 4;
#pragma unroll
    for (int i = 0; i < 4; i++) {
        float4 o = make_float4(acc[i][0], acc[i][1], acc[i][2], acc[i][3]);
        *(float4*)(C + (size_t)(m0 + i) * DIM + n0) = o;
    }
}

// ---------------- residual + LayerNorm ----------------
__global__ void add_ln_k(const float* __restrict__ a, const float* __restrict__ r,
                         const float* __restrict__ g, const float* __restrict__ bt,
                         float* __restrict__ out) {
    int row = blockIdx.x, t = threadIdx.x;
    __shared__ float sh[8];
    float4 va = ((const float4*)(a + (size_t)row * DIM))[t];
    float4 vr = ((const float4*)(r + (size_t)row * DIM))[t];
    float v0 = va.x + vr.x, v1 = va.y + vr.y, v2 = va.z + vr.z, v3 = va.w + vr.w;
    float mean = blocksum256(v0 + v1 + v2 + v3, sh) * (1.f / DIM);
    float d0 = v0 - mean, d1 = v1 - mean, d2 = v2 - mean, d3 = v3 - mean;
    float var = blocksum256(d0 * d0 + d1 * d1 + d2 * d2 + d3 * d3, sh) * (1.f / DIM);
    float rstd = rsqrtf(var + 1e-5f);
    float4 gg = ((const float4*)g)[t], bb = ((const float4*)bt)[t];
    float4 o;
    o.x = d0 * rstd * gg.x + bb.x;
    o.y = d1 * rstd * gg.y + bb.y;
    o.z = d2 * rstd * gg.z + bb.z;
    o.w = d3 * rstd * gg.w + bb.w;
    ((float4*)(out + (size_t)row * DIM))[t] = o;
}

// ---------------- router ----------------
__global__ void router_k(const float* __restrict__ rw, const float* __restrict__ rb,
                         float* __restrict__ out_logits, float* __restrict__ out_topi) {
    int n = blockIdx.x, t = threadIdx.x;
    int e = t >> 5, lane = t & 31;
    const float* xr = g_x1 + (size_t)n * DIM;
    const float* wr = rw + (size_t)e * DIM;
    float s = 0.f;
    for (int k = lane; k < DIM; k += 32) s = fmaf(xr[k], wr[k], s);
#pragma unroll
    for (int o = 16; o; o >>= 1) s += __shfl_xor_sync(0xFFFFFFFFu, s, o);
    __shared__ float lg[8];
    if (lane == 0) lg[e] = s + rb[e];
    __syncthreads();
    if (t == 0) {
        float l[8], p[8];
        float mx = -1e30f;
#pragma unroll
        for (int q = 0; q < 8; q++) { l[q] = lg[q]; mx = fmaxf(mx, l[q]); }
        float sum = 0.f;
#pragma unroll
        for (int q = 0; q < 8; q++) { p[q] = expf(l[q] - mx); sum += p[q]; }
        float inv = 1.f / sum;
#pragma unroll
        for (int q = 0; q < 8; q++) p[q] *= inv;
        int i1 = 0; float m1 = p[0];
#pragma unroll
        for (int q = 1; q < 8; q++) if (p[q] > m1) { m1 = p[q]; i1 = q; }
        int i2 = -1; float m2 = -1.f;
#pragma unroll
        for (int q = 0; q < 8; q++) if (q != i1 && p[q] > m2) { m2 = p[q]; i2 = q; }
#pragma unroll
        for (int q = 0; q < 8; q++) g_logits[n * 8 + q] = l[q];
        g_ti[n * 2] = i1;  g_ti[n * 2 + 1] = i2;
        g_tv[n * 2] = m1;  g_tv[n * 2 + 1] = m2;
        if (out_logits) {
#pragma unroll
            for (int q = 0; q < 8; q++) out_logits[n * 8 + q] = l[q];
        }
        if (out_topi) { out_topi[n * 2] = (float)i1; out_topi[n * 2 + 1] = (float)i2; }
    }
}

// ---------------- capacity selection ----------------
__global__ void cap_select_k() {
    int e = blockIdx.x, t = threadIdx.x;
    __shared__ unsigned long long keys[NTOK];
    __shared__ int s_cnt;
    if (t == 0) s_cnt = 0;
    __syncthreads();
    int local = 0;
    for (int n = t; n < NTOK; n += 1024) {
        bool cand = (g_ti[n * 2] == e) || (g_ti[n * 2 + 1] == e);
        float v = cand ? g_logits[n * NEXP + e] : NEGV;
        unsigned u = __float_as_uint(v);
        u = (u & 0x80000000u) ? ~u : (u | 0x80000000u);
        unsigned long long key = ((unsigned long long)u << 32) | (unsigned)(0xFFFFFFFFu - (unsigned)n);
        keys[n] = ~key;
        local += cand ? 1 : 0;
    }
    atomicAdd(&s_cnt, local);
    __syncthreads();
    for (int k = 2; k <= NTOK; k <<= 1)
        for (int j = k >> 1; j > 0; j >>= 1) {
            for (int base = t; base < NTOK; base += 1024) {
                int l = base ^ j;
                if (l > base) {
                    bool up = ((base & k) == 0);
                    unsigned long long a = keys[base], b = keys[l];
                    if ((a > b) == up) { keys[base] = b; keys[l] = a; }
                }
            }
            __syncthreads();
        }
    int cnt = min(s_cnt, CAPN);
    if (t == 0) g_cnt[e] = cnt;
    for (int c = t; c < CAPN; c += 1024) {
        if (c < cnt) {
            unsigned long long key = ~keys[c];
            int tok = (int)(0xFFFFFFFFu - (unsigned)(key & 0xFFFFFFFFu));
            g_tok[e * CAPN + c] = tok;
            g_w[e * CAPN + c] = (g_ti[tok * 2] == e) ? g_tv[tok * 2] : g_tv[tok * 2 + 1];
        } else {
            g_tok[e * CAPN + c] = 0;
            g_w[e * CAPN + c] = 0.f;
        }
    }
}

__global__ void zero_moe_k() {
    size_t i = (size_t)blockIdx.x * blockDim.x + threadIdx.x;
    ((float4*)g_moe)[i] = make_float4(0.f, 0.f, 0.f, 0.f);
}

// ---------------- host ----------------
extern "C" void kernel_launch(void* const* d_in, const int* in_sizes, int n_in,
                              void* d_out, int out_size) {
    const float* x   = (const float*)d_in[0];
    const float* ipw = (const float*)d_in[1];
    const float* ipb = (const float*)d_in[2];
    const float* opw = (const float*)d_in[3];
    const float* opb = (const float*)d_in[4];
    const float* n1g = (const float*)d_in[5];
    const float* n1b = (const float*)d_in[6];
    const float* n2g = (const float*)d_in[7];
    const float* n2b = (const float*)d_in[8];
    const float* rw  = (const float*)d_in[9];
    const float* rb  = (const float*)d_in[10];
    const float* gw  = (const float*)d_in[11];
    const float* gb  = (const float*)d_in[12];
    const float* vw  = (const float*)d_in[13];
    const float* vb  = (const float*)d_in[14];
    const float* wow = (const float*)d_in[15];
    const float* wob = (const float*)d_in[16];
    float* out = (float*)d_out;

    const int SM_G128 = 65536;
    const int SM_GV   = 66560;
    cudaFuncSetAttribute(gemm_mma,      cudaFuncAttributeMaxDynamicSharedMemorySize, SM_G128);
    cudaFuncSetAttribute(moe_gatval_mma, cudaFuncAttributeMaxDynamicSharedMemorySize, SM_GV);
    cudaFuncSetAttribute(moe_wo_mma,    cudaFuncAttributeMaxDynamicSharedMemorySize, SM_G128);

    static cudaStream_t s2 = nullptr;
    static cudaEvent_t ev0 = nullptr, ev2 = nullptr, ev3 = nullptr, ev4 = nullptr;
    if (!s2) {
        cudaStreamCreateWithFlags(&s2, cudaStreamNonBlocking);
        cudaEventCreateWithFlags(&ev0, cudaEventDisableTiming);
        cudaEventCreateWithFlags(&ev2, cudaEventDisableTiming);
        cudaEventCreateWithFlags(&ev3, cudaEventDisableTiming);
        cudaEventCreateWithFlags(&ev4, cudaEventDisableTiming);
    }

    void *p_qkv, *p_qh, *p_kh, *p_vh, *p_ao, *p_tmp, *p_x1, *p_moe, *p_sc;
    void *p_xc, *p_wipc, *p_qc, *p_kc, *p_vc, *p_aoc, *p_wopc;
    void *p_x1c, *p_gwc, *p_vwc, *p_woc, *p_hc;
    cudaGetSymbolAddress(&p_qkv, g_qkv);  cudaGetSymbolAddress(&p_qh, g_qh);
    cudaGetSymbolAddress(&p_kh, g_kh);    cudaGetSymbolAddress(&p_vh, g_vh);
    cudaGetSymbolAddress(&p_ao, g_ao);    cudaGetSymbolAddress(&p_tmp, g_tmp);
    cudaGetSymbolAddress(&p_x1, g_x1);    cudaGetSymbolAddress(&p_moe, g_moe);
    cudaGetSymbolAddress(&p_sc, g_sc);
    cudaGetSymbolAddress(&p_xc, g_xc);    cudaGetSymbolAddress(&p_wipc, g_wipc);
    cudaGetSymbolAddress(&p_qc, g_qc);    cudaGetSymbolAddress(&p_kc, g_kc);
    cudaGetSymbolAddress(&p_vc, g_vc);
    cudaGetSymbolAddress(&p_aoc, g_aoc);  cudaGetSymbolAddress(&p_wopc, g_wopc);
    cudaGetSymbolAddress(&p_x1c, g_x1c);
    cudaGetSymbolAddress(&p_gwc, g_gwc);  cudaGetSymbolAddress(&p_vwc, g_vwc);
    cudaGetSymbolAddress(&p_woc, g_woc);  cudaGetSymbolAddress(&p_hc, g_hc);

    float* out_logits = (out_size >= NTOK * DIM + NTOK * NEXP) ? out + NTOK * DIM : nullptr;
    float* out_topi   = (out_size >= NTOK * DIM + NTOK * NEXP + NTOK * 2)
                            ? out + NTOK * DIM + NTOK * NEXP : nullptr;

    zero_moe_k<<<NTOK * DIM / 4 / 256, 256>>>();
    rope_tables_k<<<(SEQ * 32 + 255) / 256, 256>>>();

    // ---- fork: bulk MoE weight conversions (2-term) overlap the attention phase ----
    cudaEventRecord(ev0, 0);
    cudaStreamWaitEvent(s2, ev0, 0);
    conv2_k<<<(long)NEXP * FF * DIM / 256, 256, 0, s2>>>(gw, DIM, (__nv_bfloat16*)p_gwc, 10, 1, (long)NEXP * FF * DIM);
    conv2_k<<<(long)NEXP * FF * DIM / 256, 256, 0, s2>>>(vw, DIM, (__nv_bfloat16*)p_vwc, 10, 1, (long)NEXP * FF * DIM);
    conv2_k<<<(long)NEXP * DIM * FF / 256, 256, 0, s2>>>(wow, FF, (__nv_bfloat16*)p_woc, 12, 1, (long)NEXP * DIM * FF);
    cudaEventRecord(ev2, s2);

    // ---- attention: projections in 3-term bf16, core attention fp32 ----
    conv3_k<<<(long)NTOK * DIM / 256, 256>>>(x, DIM, (__nv_bfloat16*)p_xc, 10, 0, (long)NTOK * DIM);
    conv3_k<<<(long)D3 * DIM / 256, 256>>>(ipw, DIM, (__nv_bfloat16*)p_wipc, 10, 1, (long)D3 * DIM);
    gemm_mma<<<dim3(32, 24, 1), 128, SM_G128>>>(
        (__nv_bfloat16*)p_xc, 3072, 0, (__nv_bfloat16*)p_wipc, 3072, 0,
        ipb, 1.f, (float*)p_qkv, D3, 1, 0, 0, 3072);
    rope_apply_k<<<(2 * NTOK * NH * 32) / 256, 256>>>();

    conv3_k<<<(long)NTOK * DIM / 256, 256>>>((float*)p_qkv,           D3, (__nv_bfloat16*)p_qc, 10, 0, (long)NTOK * DIM);
    conv3_k<<<(long)NTOK * DIM / 256, 256>>>((float*)p_qkv + DIM,     D3, (__nv_bfloat16*)p_kc, 10, 0, (long)NTOK * DIM);
    conv3_k<<<(long)NTOK * DIM / 256, 256>>>((float*)p_qkv + 2 * DIM, D3, (__nv_bfloat16*)p_vc, 10, 0, (long)NTOK * DIM);
    gemm_mma<<<dim3(32, 8, 1), 128, SM_G128>>>(
        (__nv_bfloat16*)p_qc, 3072, 0, (__nv_bfloat16*)p_wipc, 3072, 0,
        ipb, 1.f, (float*)p_qh, DIM, 1, 0, 0, 3072);
    gemm_mma<<<dim3(32, 8, 1), 128, SM_G128>>>(
        (__nv_bfloat16*)p_kc, 3072, 0, (__nv_bfloat16*)p_wipc + (long)DIM * 3072, 3072, 0,
        ipb + DIM, 1.f, (float*)p_kh, DIM, 1, 0, 0, 3072);
    gemm_mma<<<dim3(32, 8, 1), 128, SM_G128>>>(
        (__nv_bfloat16*)p_vc, 3072, 0, (__nv_bfloat16*)p_wipc + 2L * DIM * 3072, 3072, 0,
        ipb + 2 * DIM, 1.f, (float*)p_vh, DIM, 1, 0, 0, 3072);

    attn_scores_k<<<dim3(SEQ / 64, SEQ / 64, 4 * NH), 256>>>();
    softmax_k<<<4 * NH * SEQ, 256>>>();
    attn_av_k<<<dim3(SEQ / 64, 4 * NH), 256>>>();

    conv3_k<<<(long)NTOK * DIM / 256, 256>>>((float*)p_ao, DIM, (__nv_bfloat16*)p_aoc, 10, 0, (long)NTOK * DIM);
    conv3_k<<<(long)DIM * DIM / 256, 256>>>(opw, DIM, (__nv_bfloat16*)p_wopc, 10, 1, (long)DIM * DIM);
    gemm_mma<<<dim3(32, 8, 1), 128, SM_G128>>>(
        (__nv_bfloat16*)p_aoc, 3072, 0, (__nv_bfloat16*)p_wopc, 3072, 0,
        opb, 1.f, (float*)p_tmp, DIM, 1, 0, 0, 3072);
    add_ln_k<<<NTOK, 256>>>(x, (float*)p_tmp, n1g, n1b, (float*)p_x1);

    // ---- fork: x1c conversion (2-term) overlaps router + capacity selection ----
    cudaEventRecord(ev3, 0);
    cudaStreamWaitEvent(s2, ev3, 0);
    conv2_k<<<(long)NTOK * DIM / 256, 256, 0, s2>>>((float*)p_x1, DIM, (__nv_bfloat16*)p_x1c, 10, 0, (long)NTOK * DIM);
    cudaEventRecord(ev4, s2);

    router_k<<<NTOK, 256>>>(rw, rb, out_logits, out_topi);
    cap_select_k<<<NEXP, 1024>>>();

    // ---- MoE (2-term) ----
    cudaStreamWaitEvent(0, ev2, 0);
    cudaStreamWaitEvent(0, ev4, 0);
    moe_gatval_mma<<<dim3(16, 64, 8), 128, SM_GV>>>(gb, vb, (float*)p_sc);
    conv2_k<<<(long)NEXP * CAPN * FF / 256, 256>>>((float*)p_sc, FF, (__nv_bfloat16*)p_hc, 12, 0, (long)NEXP * CAPN * FF);
    moe_wo_mma<<<dim3(16, 8, 8), 128, SM_G128>>>(wob);

    add_ln_k<<<NTOK, 256>>>((float*)p_x1, (float*)p_moe, n2g, n2b, out);
}